// round 12
// baseline (speedup 1.0000x reference)
#include <cuda_runtime.h>

// Problem constants
#define BB      1024
#define NPATCH  64
#define PD      192
#define KCODES  4096
#define EDIM    2048
#define VDIM    2048
#define M_TOTAL (BB * NPATCH)   // 65536 patches

// Output layout (concatenated, float32):
//   [0, B*E)             z_real
//   [B*E, ..)            z_vsa
//   [.., ..)             indices (cast to float)
//   [.., ..)             z_local
#define O_ZREAL 0
#define O_ZVSA  (BB * EDIM)
#define O_IDX   (O_ZVSA + BB * VDIM)
#define O_ZLOC  (O_IDX + BB * NPATCH)

__device__ int g_indices[M_TOTAL];

// ---------------------------------------------------------------------------
// Fused patchify + GEMM + argmax.
//
// Block: 128 patches (= 2 whole images) x all 4096 codes.
// A (128 x 192) loaded once straight from pixels (patchify fused) into smem,
// transposed [k][p], +1 pad. B (codes) streamed 256-codes x 16-k chunks with
// register prefetch to hide L2 latency, DOUBLE-BUFFERED in smem so each
// chunk needs only one __syncthreads():
//   iter kc: store regs -> buf[kc&1]; BAR; prefetch kc+1; compute buf[kc&1].
// Safety: readers of buf[x] (iter kc) finish before the BAR inside iter
// kc+1; the next write to buf[x] is at iter kc+2, after that BAR.
//
// Threads 16x16. Thread (ty,tx): patches {ty+16i, i<8}; codes in 8 float2
// slots, slot j holds codes {32j + 2tx, 32j + 2tx + 1}.
// Inner product is packed fma.rn.f32x2: exact fp32 per lane, ascending-k
// accumulation (same order as the naive reference -> argmax-stable).
// ---------------------------------------------------------------------------
#define TM 128
#define TN 256
#define KC 16
#define NCT     (KCODES / TN)    // 16 code tiles
#define KCHUNKS (PD / KC)        // 12 k chunks

#define AS_STRIDE 129            // [192][129] floats
#define BS_STRIDE 258            // 16 rows x (128 float2 + pad)

#define AS_FLOATS (PD * AS_STRIDE)     // 24768
#define BS_FLOATS (KC * BS_STRIDE)     // 4128 per buffer, x2 buffers
#define RED_FLOATS (TM * 16)           // 2048
#define RED_INTS   (TM * 16)           // 2048
#define SMEM_BYTES ((AS_FLOATS + 2 * BS_FLOATS + RED_FLOATS + RED_INTS) * 4) // 148480

__device__ __forceinline__ unsigned long long pack2(float lo, float hi) {
    unsigned long long r;
    asm("mov.b64 %0, {%1, %2};" : "=l"(r)
        : "r"(__float_as_uint(lo)), "r"(__float_as_uint(hi)));
    return r;
}
__device__ __forceinline__ void unpack2(unsigned long long v, float& lo, float& hi) {
    unsigned int l, h;
    asm("mov.b64 {%0, %1}, %2;" : "=r"(l), "=r"(h) : "l"(v));
    lo = __uint_as_float(l); hi = __uint_as_float(h);
}
__device__ __forceinline__ void fma2(unsigned long long& d,
                                     unsigned long long a, unsigned long long b) {
    asm("fma.rn.f32x2 %0, %1, %2, %0;" : "+l"(d) : "l"(a), "l"(b));
}

__global__ __launch_bounds__(256, 1)
void argmax_kernel(const float* __restrict__ pixels,
                   const float* __restrict__ codebook,
                   float* __restrict__ out) {
    extern __shared__ float smem[];
    float* As   = smem;
    float* Bs0  = smem + AS_FLOATS;          // double buffer: Bs0 / Bs0+BS_FLOATS
    float* redM = Bs0 + 2 * BS_FLOATS;
    int*   redI = (int*)(redM + RED_FLOATS);

    const int tid = threadIdx.x;
    const int ty  = tid >> 4;
    const int tx  = tid & 15;
    const int pb  = blockIdx.x * TM;          // first patch (global)
    const int b0  = blockIdx.x * 2;           // first image

    // Per-thread B staging decode (constant across all tiles/chunks).
    // i4 = t*256 + tid ; c = i4>>2 ; k4 = i4&3 ; slot fi == c (identity map:
    // slot s = tx + 16j holds codes 32j + 2tx + {0,1}).
    int st_c[4], st_k4[4];
#pragma unroll
    for (int t = 0; t < 4; t++) {
        int i4 = t * 256 + tid;
        st_c[t]  = i4 >> 2;
        st_k4[t] = i4 & 3;
    }

    // ---- Fused patchify: 2 images -> As[d][p] (d = k-dim, p = local patch).
    // pixels layout (b, ch, row, col). One float4 spans 4 cols inside one
    // 8-wide patch column block (col0 % 4 == 0).
    // d = ch*64 + (row&7)*8 + (col&7), p = img*64 + (row>>3)*8 + (col>>3).
    {
        const float4* px = (const float4*)(pixels + (size_t)b0 * 3 * 64 * 64);
        for (int i = tid; i < 2 * 3 * 64 * 16; i += 256) {   // 6144 float4
            int img = i / 3072;                // float4s per image = 3*64*16
            int rem = i - img * 3072;
            int ch  = rem >> 10;               // 64 rows * 16 f4 per channel
            int r2  = rem & 1023;
            int row = r2 >> 4;
            int col0 = (r2 & 15) << 2;
            float4 v = px[i];
            int p = (img << 6) + ((row >> 3) << 3) + (col0 >> 3);
            int d = (ch << 6) + ((row & 7) << 3) + (col0 & 7);
            As[(d + 0) * AS_STRIDE + p] = v.x;
            As[(d + 1) * AS_STRIDE + p] = v.y;
            As[(d + 2) * AS_STRIDE + p] = v.z;
            As[(d + 3) * AS_STRIDE + p] = v.w;
        }
    }

    float bestM[8];
    int   bestI[8];
#pragma unroll
    for (int i = 0; i < 8; i++) { bestM[i] = -1e30f; bestI[i] = 0; }

    __syncthreads();   // As visible to all before first compute

#pragma unroll 1
    for (int ct = 0; ct < NCT; ct++) {
        const int cb0 = ct * TN;

        unsigned long long acc[8][8];
#pragma unroll
        for (int i = 0; i < 8; i++)
#pragma unroll
            for (int j = 0; j < 8; j++) acc[i][j] = 0ULL;

        // Prefetch chunk 0 of this code tile: 256 codes x 16 k = 1024 float4.
        float4 ld[4];
#pragma unroll
        for (int t = 0; t < 4; t++)
            ld[t] = *(const float4*)(
                &codebook[(size_t)(cb0 + st_c[t]) * PD + st_k4[t] * 4]);

#pragma unroll 1
        for (int kc = 0; kc < KCHUNKS; kc++) {
            float* Bc = Bs0 + (kc & 1) * BS_FLOATS;
            // Store staged regs into this chunk's buffer. The other buffer
            // may still have laggard readers from iter kc-1 -- disjoint.
#pragma unroll
            for (int t = 0; t < 4; t++) {
                int base = st_k4[t] * 4 * BS_STRIDE + st_c[t];
                Bc[base + 0 * BS_STRIDE] = ld[t].x;
                Bc[base + 1 * BS_STRIDE] = ld[t].y;
                Bc[base + 2 * BS_STRIDE] = ld[t].z;
                Bc[base + 3 * BS_STRIDE] = ld[t].w;
            }
            __syncthreads();   // the single barrier per chunk

            // Prefetch next chunk while computing this one.
            if (kc + 1 < KCHUNKS) {
#pragma unroll
                for (int t = 0; t < 4; t++)
                    ld[t] = *(const float4*)(
                        &codebook[(size_t)(cb0 + st_c[t]) * PD
                                  + (kc + 1) * KC + st_k4[t] * 4]);
            }

#pragma unroll 4
            for (int kk = 0; kk < KC; kk++) {
                const int krow = kc * KC + kk;
                unsigned long long a2[8], b2[8];
#pragma unroll
                for (int i = 0; i < 8; i++) {
                    float av = As[krow * AS_STRIDE + ty + 16 * i];
                    a2[i] = pack2(av, av);
                }
#pragma unroll
                for (int j = 0; j < 8; j++)
                    b2[j] = *(const unsigned long long*)
                               (&Bc[kk * BS_STRIDE + 2 * (tx + 16 * j)]);
#pragma unroll
                for (int i = 0; i < 8; i++)
#pragma unroll
                    for (int j = 0; j < 8; j++)
                        fma2(acc[i][j], a2[i], b2[j]);
            }
        }

        // Fold tile into running argmax. Per-thread code index ascends with
        // (j, lane); strict '>' keeps the lowest index on exact ties.
#pragma unroll
        for (int i = 0; i < 8; i++)
#pragma unroll
            for (int j = 0; j < 8; j++) {
                float lo, hi;
                unpack2(acc[i][j], lo, hi);
                int c0 = cb0 + 2 * tx + 32 * j;
                if (lo > bestM[i]) { bestM[i] = lo; bestI[i] = c0; }
                if (hi > bestM[i]) { bestM[i] = hi; bestI[i] = c0 + 1; }
            }
    }

    // Cross-thread reduce: 16 tx partials per patch; lowest index wins ties.
    __syncthreads();   // last chunk's Bc reads complete before smem reuse
#pragma unroll
    for (int i = 0; i < 8; i++) {
        int p = ty + 16 * i;
        redM[p * 16 + tx] = bestM[i];
        redI[p * 16 + tx] = bestI[i];
    }
    __syncthreads();
    if (tid < TM) {
        int p = tid;
        float m  = redM[p * 16];
        int   bi = redI[p * 16];
#pragma unroll
        for (int t = 1; t < 16; t++) {
            float v  = redM[p * 16 + t];
            int   vi = redI[p * 16 + t];
            if (v > m || (v == m && vi < bi)) { m = v; bi = vi; }
        }
        g_indices[pb + p] = bi;
        out[O_IDX + pb + p] = (float)bi;
    }
}

// ---------------------------------------------------------------------------
// z_real = mean of 64 gathered embedding rows; z_local = mean of 9 AGENT rows.
// Embeddings (32 MB) stay L2-resident across the 1024 images.
// ---------------------------------------------------------------------------
__global__ void means_kernel(const float* __restrict__ embeddings, float* __restrict__ out) {
    __shared__ int idx_s[64];
    const int b   = blockIdx.y;
    const int tid = threadIdx.x;
    if (tid < 64) idx_s[tid] = g_indices[b * 64 + tid];
    __syncthreads();

    const int e = blockIdx.x * 256 + tid;
    // AGENT: p = 8r+c, r,c in [3,6): {27,28,29, 35,36,37, 43,44,45}
    const unsigned long long AGENT_MASK = (7ULL << 27) | (7ULL << 35) | (7ULL << 43);
    float s = 0.0f, sl = 0.0f;
#pragma unroll
    for (int p = 0; p < 64; p++) {
        float v = embeddings[(size_t)idx_s[p] * EDIM + e];
        s += v;
        if ((AGENT_MASK >> p) & 1ULL) sl += v;
    }
    out[O_ZREAL + (size_t)b * EDIM + e] = s * (1.0f / 64.0f);
    out[O_ZLOC  + (size_t)b * EDIM + e] = sl * (1.0f / 9.0f);
}

// ---------------------------------------------------------------------------
// z_vsa: bound = (cb + pos) mod 2 == XOR for {0,1}; sum over 16 CENTRAL
// patches, threshold > 8.
// ---------------------------------------------------------------------------
__global__ void vsa_kernel(const float* __restrict__ cvsa,
                           const float* __restrict__ proles,
                           float* __restrict__ out) {
    __shared__ int idxc[16];
    const int b   = blockIdx.y;
    const int tid = threadIdx.x;
    if (tid < 16) {
        int p = (2 + (tid >> 2)) * 8 + 2 + (tid & 3);   // CENTRAL[tid]
        idxc[tid] = g_indices[b * 64 + p];
    }
    __syncthreads();

    const int v = blockIdx.x * 256 + tid;
    int cnt = 0;
#pragma unroll
    for (int j = 0; j < 16; j++) {
        int p = (2 + (j >> 2)) * 8 + 2 + (j & 3);
        float cb = cvsa[(size_t)idxc[j] * VDIM + v];
        float pr = proles[(size_t)p * VDIM + v];
        cnt += (cb != pr);
    }
    out[O_ZVSA + (size_t)b * VDIM + v] = (cnt > 8) ? 1.0f : 0.0f;
}

// ---------------------------------------------------------------------------
extern "C" void kernel_launch(void* const* d_in, const int* in_sizes, int n_in,
                              void* d_out, int out_size) {
    const float* pixels     = (const float*)d_in[0];
    const float* codebook   = (const float*)d_in[1];
    const float* embeddings = (const float*)d_in[2];
    const float* cvsa       = (const float*)d_in[3];
    const float* proles     = (const float*)d_in[4];
    float* out = (float*)d_out;

    cudaFuncSetAttribute(argmax_kernel,
                         cudaFuncAttributeMaxDynamicSharedMemorySize, SMEM_BYTES);

    argmax_kernel<<<M_TOTAL / TM, 256, SMEM_BYTES>>>(pixels, codebook, out);

    dim3 gm(EDIM / 256, BB);
    means_kernel<<<gm, 256>>>(embeddings, out);

    dim3 gv(VDIM / 256, BB);
    vsa_kernel<<<gv, 256>>>(cvsa, proles, out);
}